// round 12
// baseline (speedup 1.0000x reference)
#include <cuda_runtime.h>
#include <cuda_bf16.h>
#include <cstdint>

// CTC loss forward — single fused kernel, prep/scan overlapped.
// Grid = 32 scan CTAs (bid 0..31, wave-1 resident) + 32*125 prep CTAs.
// prep CTA: 8 logp rows -> halo e-table g_E[b][t][lane*12+j] (e at trellis
//           position 7*lane-3+j, 0 if invalid); sets g_ready[b][tgroup].
// scan CTA b: wid0 = forward alpha (t=1..m), wid1 = backward gamma
//           (t=il-1..m+1), meet-in-the-middle; cp.async.bulk 3-slot rings,
//           issues gated on g_ready flags (acquire loads); 2 steps/iter
//           (redundant halo), renorm every 2 iters, per-lane block floating
//           point. Last scan CTA reduces g_loss -> out. Flags+counter reset
//           each run => graph-replay safe.

#define TT 1000
#define BB 32
#define CC 1000
#define SS 100
#define RF 384                 // floats per table row (32 lanes x 12)
#define RB (RF * 4)            // 1536 bytes
#define CHR 8                  // rows per scan chunk (even)
#define NSLOT 3
#define CHUNK_F (CHR * RF)     // 3072
#define NTG 125                // 8-row production groups
#define SCAN_SMEM ((2 * NSLOT * CHUNK_F + 256) * 4 + 32 * 4 + 2 * NSLOT * 8)

#define LOG2E_F 1.4426950408889634f
#define LN2_F 0.6931471805599453f
#define EDEAD (-(1 << 28))

__device__ float g_E[BB][TT][RF];      // 49 MB static scratch
__device__ float g_loss[BB];
__device__ int g_done;                 // reset by last scan CTA each run
__device__ int g_ready[BB][NTG];       // reset by scan CTAs each run

__device__ __forceinline__ float fast_ex2(float x) {
    float y; asm("ex2.approx.ftz.f32 %0, %1;" : "=f"(y) : "f"(x)); return y;
}
__device__ __forceinline__ float fast_lg2(float x) {
    float y; asm("lg2.approx.f32 %0, %1;" : "=f"(y) : "f"(x)); return y;
}
__device__ __forceinline__ uint32_t s2u(const void* p) {
    return (uint32_t)__cvta_generic_to_shared(p);
}
__device__ __forceinline__ void mbar_init(uint64_t* mb, uint32_t cnt) {
    asm volatile("mbarrier.init.shared.b64 [%0], %1;" :: "r"(s2u(mb)), "r"(cnt) : "memory");
}
__device__ __forceinline__ void mbar_wait(uint64_t* mb, uint32_t parity) {
    asm volatile(
        "{\n\t.reg .pred P;\n\t"
        "WL%=:\n\t"
        "mbarrier.try_wait.parity.acquire.cta.shared::cta.b64 P, [%0], %1, 0x989680;\n\t"
        "@P bra WD%=;\n\t"
        "bra WL%=;\n\t"
        "WD%=:\n\t}"
        :: "r"(s2u(mb)), "r"(parity) : "memory");
}
__device__ __forceinline__ void bulk_in(uint32_t dst, const void* src, uint32_t bytes,
                                        uint64_t* mb) {
    asm volatile("mbarrier.arrive.expect_tx.shared.b64 _, [%0], %1;"
                 :: "r"(s2u(mb)), "r"(bytes) : "memory");
    asm volatile("cp.async.bulk.shared::cta.global.mbarrier::complete_tx::bytes "
                 "[%0], [%1], %2, [%3];"
                 :: "r"(dst), "l"(src), "r"(bytes), "r"(s2u(mb)) : "memory");
}
__device__ __forceinline__ void wait_groups(int b, int glo, int ghi) {
    for (int g = glo; g <= ghi; g++) {
        unsigned v;
        do {
            asm volatile("ld.acquire.gpu.global.u32 %0, [%1];"
                         : "=r"(v) : "l"(&g_ready[b][g]) : "memory");
        } while (v == 0);
    }
}
__device__ __forceinline__ float pow2_clamped(int d) {
    int u = 127 + d; if (u < 0) u = 0;
    return __uint_as_float((unsigned)u << 23);
}
__device__ __forceinline__ float skip_into(const int* __restrict__ tg, int b, int Lv, int p) {
    if ((p & 1) && p < Lv) {
        int si = (p - 1) >> 1;
        if (si > 0) {
            int c0 = tg[b * SS + si];
            int c1 = tg[b * SS + si - 1];
            return (c0 != 0 && c0 != c1) ? 1.0f : 0.0f;
        }
    }
    return 0.0f;
}

// ---- forward pair body (2 time steps); RN: renormalize mantissas ----
template <bool RN>
__device__ __forceinline__ void fpair(float a[7], int& E,
                                      const float* rowA, const float* rowB,
                                      const float skA[9], int lane) {
    const float4* pA = (const float4*)rowA;
    const float4* pB = (const float4*)rowB;
    float4 A0 = pA[0], A1 = pA[1], A2 = pA[2];
    float4 B0 = pB[0], B1 = pB[1], B2 = pB[2];
    float eA[9] = {A0.y, A0.z, A0.w, A1.x, A1.y, A1.z, A1.w, A2.x, A2.y};
    float eB[7] = {B0.w, B1.x, B1.y, B1.z, B1.w, B2.x, B2.y};

    float h3 = __shfl_up_sync(~0u, a[3], 1);
    float h4 = __shfl_up_sync(~0u, a[4], 1);
    float h5 = __shfl_up_sync(~0u, a[5], 1);
    float h6 = __shfl_up_sync(~0u, a[6], 1);
    int   Ep = __shfl_up_sync(~0u, E, 1);
    if (lane == 0) { h3 = 0.0f; h4 = 0.0f; h5 = 0.0f; h6 = 0.0f; }

    int Em = (E > Ep) ? E : Ep;
    float sa = pow2_clamped(E - Em);
    float sp = pow2_clamped(Ep - Em);
    float X[11];
    X[0] = h3 * sp; X[1] = h4 * sp; X[2] = h5 * sp; X[3] = h6 * sp;
#pragma unroll
    for (int j = 0; j < 7; j++) X[4 + j] = a[j] * sa;

    float bt[9];
#pragma unroll
    for (int i = 0; i < 9; i++)
        bt[i] = fmaf(skA[i], X[i], X[i + 2] + X[i + 1]) * eA[i];
    float n[7];
#pragma unroll
    for (int j = 0; j < 7; j++)
        n[j] = fmaf(skA[j + 2], bt[j], bt[j + 2] + bt[j + 1]) * eB[j];

    if (RN) {
        float mm = fmaxf(fmaxf(fmaxf(n[0], n[1]), fmaxf(n[2], n[3])),
                         fmaxf(fmaxf(n[4], n[5]), n[6]));
        unsigned ub = __float_as_uint(mm) >> 23;
        int shift = 127 - (int)ub;          // ub=0 (dead lane) -> 127, exact
        float f = __uint_as_float((unsigned)(shift + 127) << 23);
        E = Em - shift;
#pragma unroll
        for (int j = 0; j < 7; j++) a[j] = n[j] * f;
    } else {
        E = Em;
#pragma unroll
        for (int j = 0; j < 7; j++) a[j] = n[j];
    }
}

// ---- backward pair body ----
template <bool RN>
__device__ __forceinline__ void bpair(float u[7], int& E,
                                      const float* rowA, const float* rowB,
                                      const float sB9[9], int lane) {
    const float4* pA = (const float4*)rowA;
    const float4* pB = (const float4*)rowB;
    float4 A0 = pA[0], A1 = pA[1], A2 = pA[2];
    float4 B0 = pB[0], B1 = pB[1], B2 = pB[2];
    float eA[9] = {A0.w, A1.x, A1.y, A1.z, A1.w, A2.x, A2.y, A2.z, A2.w};
    float eB[7] = {B0.w, B1.x, B1.y, B1.z, B1.w, B2.x, B2.y};

    float q0 = __shfl_down_sync(~0u, u[0], 1);
    float q1 = __shfl_down_sync(~0u, u[1], 1);
    float q2 = __shfl_down_sync(~0u, u[2], 1);
    float q3 = __shfl_down_sync(~0u, u[3], 1);
    int   Eq = __shfl_down_sync(~0u, E, 1);
    if (lane == 31) { q0 = 0.0f; q1 = 0.0f; q2 = 0.0f; q3 = 0.0f; }

    int Em = (E > Eq) ? E : Eq;
    float sa = pow2_clamped(E - Em);
    float sq = pow2_clamped(Eq - Em);
    float X[11];
#pragma unroll
    for (int j = 0; j < 7; j++) X[j] = u[j] * sa;
    X[7] = q0 * sq; X[8] = q1 * sq; X[9] = q2 * sq; X[10] = q3 * sq;

    float v[9];
#pragma unroll
    for (int i = 0; i < 9; i++)
        v[i] = fmaf(sB9[i], X[i + 2], X[i] + X[i + 1]) * eA[i];
    float n[7];
#pragma unroll
    for (int j = 0; j < 7; j++)
        n[j] = fmaf(sB9[j], v[j + 2], v[j] + v[j + 1]) * eB[j];

    if (RN) {
        float mm = fmaxf(fmaxf(fmaxf(n[0], n[1]), fmaxf(n[2], n[3])),
                         fmaxf(fmaxf(n[4], n[5]), n[6]));
        unsigned ub = __float_as_uint(mm) >> 23;
        int shift = 127 - (int)ub;
        float f = __uint_as_float((unsigned)(shift + 127) << 23);
        E = Em - shift;
#pragma unroll
        for (int j = 0; j < 7; j++) u[j] = n[j] * f;
    } else {
        E = Em;
#pragma unroll
        for (int j = 0; j < 7; j++) u[j] = n[j];
    }
}

__global__ void __launch_bounds__(256, 2)
ctc_all(const float* __restrict__ logp,
        const int* __restrict__ targets,
        const int* __restrict__ input_lens,
        const int* __restrict__ target_lens,
        float* __restrict__ out) {
    extern __shared__ __align__(16) float dsm[];
    const int bid = blockIdx.x;
    const int tid = threadIdx.x;

    if (bid >= BB) {
        // ================= prep CTA: 8 rows of the halo e-table ============
        const int j = bid - BB;
        const int b = j & 31;
        const int seq = j >> 5;                            // 0..124
        const int tg = (seq & 1) ? (NTG - 1 - (seq >> 1)) : (seq >> 1);
        const int t0 = tg * 8;
        float* rows = dsm;                                 // 8 * CC floats
#pragma unroll
        for (int r = 0; r < 8; r++) {
            const float4* s = (const float4*)(logp + ((long)(t0 + r) * BB + b) * CC);
            if (tid < 250) ((float4*)(rows + r * CC))[tid] = s[tid];
        }
        __syncthreads();
        const int Lv = 2 * target_lens[b] + 1;
        for (int o = tid; o < 8 * RF; o += 256) {
            int r = o / RF, q = o - r * RF;
            int lane = q / 12, jx = q - lane * 12;
            int l = 7 * lane - 3 + jx;
            float v = 0.0f;
            if (l >= 0 && l < Lv) {
                int lbl = (l & 1) ? targets[b * SS + (l >> 1)] : 0;
                v = fast_ex2(rows[r * CC + lbl] * LOG2E_F);
            }
            g_E[b][t0 + r][q] = v;
        }
        __threadfence();
        __syncthreads();
        if (tid == 0)
            asm volatile("st.release.gpu.global.u32 [%0], %1;"
                         :: "l"(&g_ready[b][tg]), "r"(1) : "memory");
        return;
    }

    // ===================== scan CTA (2 warps) ==============================
    if (tid >= 64) return;
    float* ringF = dsm;
    float* ringB = dsm + NSLOT * CHUNK_F;
    float* xu = ringB + NSLOT * CHUNK_F;        // 256
    int* xE = (int*)(xu + 256);                 // 32
    uint64_t* mbF = (uint64_t*)(xE + 32);
    uint64_t* mbB = mbF + NSLOT;

    const int b = bid;
    const int wid = tid >> 5;
    const int lane = tid & 31;
    const int p = 7 * lane;

    const int il = input_lens[b];
    const int tl = target_lens[b];
    const int Lv = 2 * tl + 1;
    const int end1 = 2 * tl, end2 = 2 * tl - 1;
    const int m = ((il - 1) >> 1) & ~1;         // even forward step count
    int remB = il - 2 - m; if (remB < 0) remB = 0;
    const int tailB = remB & 1;
    const int bLo = m + 1 + tailB;
    int cntB = il - 1 - bLo; if (cntB < 0) cntB = 0;
    const bool combine = (il > 1);

    if (tid == 0) {
        for (int q = 0; q < NSLOT; q++) { mbar_init(&mbF[q], 1); mbar_init(&mbB[q], 1); }
        asm volatile("fence.proxy.async.shared::cta;" ::: "memory");
    }
    asm volatile("bar.sync 1, 64;" ::: "memory");

    if (wid == 0) {
        // ================= forward consumer =================
        float skA[9];
#pragma unroll
        for (int i = 0; i < 9; i++) skA[i] = skip_into(targets, b, Lv, p - 2 + i);

        float a[7];
#pragma unroll
        for (int j = 0; j < 7; j++) a[j] = 0.0f;
        int E = 0;
        if (lane == 0) {
            const float* row0 = logp + (long)b * CC;
            a[0] = fast_ex2(row0[0] * LOG2E_F);
            if (Lv > 1) a[1] = fast_ex2(row0[targets[b * SS]] * LOG2E_F);
        }

        const int nCh = (m + CHR - 1) / CHR;
        for (int c = 0; c < NSLOT; c++) {
            if (lane == 0 && c < nCh) {
                int t0r = 1 + CHR * c;
                int rows_c = m - CHR * c; if (rows_c > CHR) rows_c = CHR;
                wait_groups(b, t0r >> 3, (t0r + rows_c - 1) >> 3);
                bulk_in(s2u(ringF) + (c % NSLOT) * (CHUNK_F * 4), &g_E[b][t0r][0],
                        rows_c * RB, &mbF[c % NSLOT]);
            }
        }

        for (int c = 0; c < nCh; c++) {
            mbar_wait(&mbF[c % NSLOT], (uint32_t)((c / NSLOT) & 1));
            int rows_c = m - CHR * c; if (rows_c > CHR) rows_c = CHR;
            int pairs = rows_c >> 1;
            const float* base = ringF + (c % NSLOT) * CHUNK_F + lane * 12;
            int q = 0;
            for (; q + 2 <= pairs; q += 2) {
                fpair<false>(a, E, base + (2 * q) * RF, base + (2 * q + 1) * RF, skA, lane);
                fpair<true >(a, E, base + (2 * q + 2) * RF, base + (2 * q + 3) * RF, skA, lane);
            }
            if (q < pairs)
                fpair<true>(a, E, base + (2 * q) * RF, base + (2 * q + 1) * RF, skA, lane);

            int c2 = c + NSLOT;
            if (lane == 0 && c2 < nCh) {
                int t0r = 1 + CHR * c2;
                int rows_n = m - CHR * c2; if (rows_n > CHR) rows_n = CHR;
                wait_groups(b, t0r >> 3, (t0r + rows_n - 1) >> 3);
                bulk_in(s2u(ringF) + (c2 % NSLOT) * (CHUNK_F * 4), &g_E[b][t0r][0],
                        rows_n * RB, &mbF[c2 % NSLOT]);
            }
        }

        asm volatile("bar.sync 1, 64;" ::: "memory");   // meet

        float g[7];
        int Egam;
        if (combine) {
            float uu[7];
#pragma unroll
            for (int j = 0; j < 7; j++) uu[j] = xu[lane * 8 + j];
            float u7 = (lane < 31) ? xu[(lane + 1) * 8 + 0] : 0.0f;
            float u8 = (lane < 31) ? xu[(lane + 1) * 8 + 1] : 0.0f;
            int Eb = xE[lane];
            int Ebn = (lane < 31) ? xE[lane + 1] : Eb;
            int Em2 = (Eb > Ebn) ? Eb : Ebn;
            float su = pow2_clamped(Eb - Em2);
            float sn = pow2_clamped(Ebn - Em2);
            u7 *= sn; u8 *= sn;
            float sB[7];
#pragma unroll
            for (int j = 0; j < 7; j++) sB[j] = skip_into(targets, b, Lv, p + j + 2);
#pragma unroll
            for (int j = 0; j < 5; j++)
                g[j] = su * fmaf(sB[j], uu[j + 2], uu[j] + uu[j + 1]);
            g[5] = fmaf(sB[5], u7, su * (uu[5] + uu[6]));
            g[6] = su * uu[6] + fmaf(sB[6], u8, u7);
            Egam = Em2;
        } else {
#pragma unroll
            for (int j = 0; j < 7; j++) {
                int l = p + j;
                g[j] = (l == end1 || l == end2) ? 1.0f : 0.0f;
            }
            Egam = 0;
        }

        float cacc = 0.0f;
#pragma unroll
        for (int j = 0; j < 7; j++) cacc = fmaf(a[j], g[j], cacc);
        int Ec = (cacc > 0.0f) ? (E + Egam) : EDEAD;
#pragma unroll
        for (int o = 16; o > 0; o >>= 1) {
            float co2 = __shfl_xor_sync(~0u, cacc, o);
            int   Eo = __shfl_xor_sync(~0u, Ec, o);
            int   Emx = (Ec > Eo) ? Ec : Eo;
            cacc = cacc * pow2_clamped(Ec - Emx) + co2 * pow2_clamped(Eo - Emx);
            Ec = Emx;
        }
        if (lane == 0) {
            float lv = -(fast_lg2(cacc) + (float)Ec) * LN2_F;
            if (!(lv <= 0.5e30f)) lv = 0.0f;     // zero_infinity (inf/nan)
            g_loss[b] = lv;
            __threadfence();
            int old = atomicAdd(&g_done, 1);
            if (old == BB - 1) {
                float sum = 0.0f;
                for (int i = 0; i < BB; i++) sum += g_loss[i];
                out[0] = sum;
                g_done = 0;                       // reset for next replay
            }
        }
    } else {
        // ================= backward consumer =================
        float sB9[9];
#pragma unroll
        for (int i = 0; i < 9; i++) sB9[i] = skip_into(targets, b, Lv, p + i + 2);

        float u[7];
        int E = 0;
#pragma unroll
        for (int j = 0; j < 7; j++) {
            int l = p + j;
            float v = 0.0f;
            if (il >= 2 && (l == end1 || l == end2)) {
                int lbl = (l & 1) ? targets[b * SS + ((l - 1) >> 1)] : 0;
                v = fast_ex2(logp[((long)(il - 1) * BB + b) * CC + lbl] * LOG2E_F);
            }
            u[j] = v;
        }

        const int nCh = (cntB + CHR - 1) / CHR;
        for (int c = 0; c < NSLOT; c++) {
            if (lane == 0 && c < nCh) {
                int hi = il - 2 - CHR * c;
                int lo = hi - CHR + 1; if (lo < bLo) lo = bLo;
                wait_groups(b, lo >> 3, hi >> 3);
                bulk_in(s2u(ringB) + (c % NSLOT) * (CHUNK_F * 4), &g_E[b][lo][0],
                        (hi - lo + 1) * RB, &mbB[c % NSLOT]);
            }
        }

        for (int c = 0; c < nCh; c++) {
            mbar_wait(&mbB[c % NSLOT], (uint32_t)((c / NSLOT) & 1));
            int hi = il - 2 - CHR * c;
            int lo = hi - CHR + 1; if (lo < bLo) lo = bLo;
            int rows_c = hi - lo + 1;
            int pairs = rows_c >> 1;
            const float* base = ringB + (c % NSLOT) * CHUNK_F + lane * 12;
            int q = 0;
            for (; q + 2 <= pairs; q += 2) {
                bpair<false>(u, E, base + (rows_c - 1 - 2 * q) * RF,
                             base + (rows_c - 2 - 2 * q) * RF, sB9, lane);
                bpair<true >(u, E, base + (rows_c - 3 - 2 * q) * RF,
                             base + (rows_c - 4 - 2 * q) * RF, sB9, lane);
            }
            if (q < pairs)
                bpair<true>(u, E, base + (rows_c - 1 - 2 * q) * RF,
                            base + (rows_c - 2 - 2 * q) * RF, sB9, lane);

            int c2 = c + NSLOT;
            if (lane == 0 && c2 < nCh) {
                int hi2 = il - 2 - CHR * c2;
                int lo2 = hi2 - CHR + 1; if (lo2 < bLo) lo2 = bLo;
                wait_groups(b, lo2 >> 3, hi2 >> 3);
                bulk_in(s2u(ringB) + (c2 % NSLOT) * (CHUNK_F * 4), &g_E[b][lo2][0],
                        (hi2 - lo2 + 1) * RB, &mbB[c2 % NSLOT]);
            }
        }

        if (tailB) {
            // one leftover backward step at t = m+1
            const float* rowT = logp + ((long)(m + 1) * BB + b) * CC;
            float e7[7];
            float lpb = __ldg(rowT);
#pragma unroll
            for (int j = 0; j < 7; j++) {
                int l = p + j;
                float lp = -1e30f;
                if (l < Lv) lp = (l & 1) ? __ldg(rowT + targets[b * SS + ((l - 1) >> 1)]) : lpb;
                e7[j] = fast_ex2(lp * LOG2E_F);
            }
            float q0 = __shfl_down_sync(~0u, u[0], 1);
            float q1 = __shfl_down_sync(~0u, u[1], 1);
            int   Eq = __shfl_down_sync(~0u, E, 1);
            if (lane == 31) { q0 = 0.0f; q1 = 0.0f; }
            int Em = (E > Eq) ? E : Eq;
            float sa = pow2_clamped(E - Em);
            float sq = pow2_clamped(Eq - Em);
            float X[9];
#pragma unroll
            for (int j = 0; j < 7; j++) X[j] = u[j] * sa;
            X[7] = q0 * sq; X[8] = q1 * sq;
            float n[7];
#pragma unroll
            for (int j = 0; j < 7; j++)
                n[j] = fmaf(sB9[j], X[j + 2], X[j] + X[j + 1]) * e7[j];
            float mm = fmaxf(fmaxf(fmaxf(n[0], n[1]), fmaxf(n[2], n[3])),
                             fmaxf(fmaxf(n[4], n[5]), n[6]));
            unsigned ub = __float_as_uint(mm) >> 23;
            int shift = 127 - (int)ub;
            float f = __uint_as_float((unsigned)(shift + 127) << 23);
            E = Em - shift;
#pragma unroll
            for (int j = 0; j < 7; j++) u[j] = n[j] * f;
        }

        if (!combine) {                          // il == 1
#pragma unroll
            for (int j = 0; j < 7; j++) {
                int l = p + j;
                u[j] = (l == end1 || l == end2) ? 1.0f : 0.0f;
            }
            E = 0;
        }
#pragma unroll
        for (int j = 0; j < 7; j++) xu[lane * 8 + j] = u[j];
        xu[lane * 8 + 7] = 0.0f;
        xE[lane] = E;
        asm volatile("bar.sync 1, 64;" ::: "memory");   // meet

        // reset flags for next graph replay (all groups were awaited above)
        for (int i = lane; i < NTG; i += 32) g_ready[b][i] = 0;
    }
}

extern "C" void kernel_launch(void* const* d_in, const int* in_sizes, int n_in,
                              void* d_out, int out_size) {
    const float* logp        = (const float*)d_in[0];
    const int*   targets     = (const int*)d_in[1];
    const int*   input_lens  = (const int*)d_in[2];
    const int*   target_lens = (const int*)d_in[3];
    float* out = (float*)d_out;

    cudaFuncSetAttribute(ctc_all, cudaFuncAttributeMaxDynamicSharedMemorySize, SCAN_SMEM);
    ctc_all<<<BB + BB * NTG, 256, SCAN_SMEM>>>(logp, targets, input_lens, target_lens, out);
}

// round 13
// speedup vs baseline: 1.3061x; 1.3061x over previous
#include <cuda_runtime.h>
#include <cuda_bf16.h>
#include <cstdint>

// CTC loss forward — one kernel, 148 CTAs (1 wave, 1 CTA/SM).
//   bid 0..31  : scan CTA for batch b (4 warps):
//                w0 = forward alpha consumer (t=1..m)
//                w1 = backward gamma consumer (t=il-1..m+1), meet in middle
//                w2/w3 = prefetcher warps: poll g_ready flags, cp.async.bulk
//                        table chunks into 3-slot rings (consumers never spin)
//   bid 32..147: persistent prep CTAs (384 thr): produce halo e-table
//                g_E[b][t][q], q=lane*12+j => e at trellis pos 7*lane-3+j,
//                in consumption-priority order; set g_ready[b][group].
// Per-lane block floating point (mantissa regs + int exponent), 2 steps/iter
// via redundant halo, renorm every 2 iters. Last scan CTA reduces -> out.

#define TT 1000
#define BB 32
#define CC 1000
#define SS 100
#define RF 384                 // floats per table row
#define RB (RF * 4)            // 1536 B
#define CHR 8                  // rows per ring chunk (== group size)
#define NSLOT 3
#define CHUNK_F (CHR * RF)     // 3072 floats
#define NTG 125                // 8-row groups per batch
#define NPREP 116
#define SMEM_BYTES (2 * NSLOT * CHUNK_F * 4 + 256 * 4 + 32 * 4 + 12 * 8 + 64)

#define LOG2E_F 1.4426950408889634f
#define LN2_F 0.6931471805599453f
#define EDEAD (-(1 << 28))

__device__ float g_E[BB][TT][RF];      // 49 MB static scratch
__device__ float g_loss[BB];
__device__ int g_done;                 // reset each run by last scan CTA
__device__ int g_ready[BB][NTG];       // reset each run by scan CTAs

__device__ __forceinline__ float fast_ex2(float x) {
    float y; asm("ex2.approx.ftz.f32 %0, %1;" : "=f"(y) : "f"(x)); return y;
}
__device__ __forceinline__ float fast_lg2(float x) {
    float y; asm("lg2.approx.f32 %0, %1;" : "=f"(y) : "f"(x)); return y;
}
__device__ __forceinline__ uint32_t s2u(const void* p) {
    return (uint32_t)__cvta_generic_to_shared(p);
}
__device__ __forceinline__ void mbar_init(uint64_t* mb, uint32_t cnt) {
    asm volatile("mbarrier.init.shared.b64 [%0], %1;" :: "r"(s2u(mb)), "r"(cnt) : "memory");
}
__device__ __forceinline__ void mbar_wait(uint64_t* mb, uint32_t parity) {
    asm volatile(
        "{\n\t.reg .pred P;\n\t"
        "WL%=:\n\t"
        "mbarrier.try_wait.parity.acquire.cta.shared::cta.b64 P, [%0], %1, 0x989680;\n\t"
        "@P bra WD%=;\n\t"
        "bra WL%=;\n\t"
        "WD%=:\n\t}"
        :: "r"(s2u(mb)), "r"(parity) : "memory");
}
__device__ __forceinline__ void mbar_arrive(uint64_t* mb) {
    asm volatile("mbarrier.arrive.shared.b64 _, [%0];" :: "r"(s2u(mb)) : "memory");
}
__device__ __forceinline__ void bulk_in(uint32_t dst, const void* src, uint32_t bytes,
                                        uint64_t* mb) {
    asm volatile("mbarrier.arrive.expect_tx.shared.b64 _, [%0], %1;"
                 :: "r"(s2u(mb)), "r"(bytes) : "memory");
    asm volatile("cp.async.bulk.shared::cta.global.mbarrier::complete_tx::bytes "
                 "[%0], [%1], %2, [%3];"
                 :: "r"(dst), "l"(src), "r"(bytes), "r"(s2u(mb)) : "memory");
}
__device__ __forceinline__ void wait_groups(int b, int glo, int ghi) {
    for (int g = glo; g <= ghi; g++) {
        unsigned v;
        do {
            asm volatile("ld.acquire.gpu.global.u32 %0, [%1];"
                         : "=r"(v) : "l"(&g_ready[b][g]) : "memory");
        } while (v == 0);
    }
}
__device__ __forceinline__ float pow2_clamped(int d) {
    int u = 127 + d; if (u < 0) u = 0;
    return __uint_as_float((unsigned)u << 23);
}
__device__ __forceinline__ float skip_into(const int* __restrict__ tg, int b, int Lv, int p) {
    if ((p & 1) && p < Lv) {
        int si = (p - 1) >> 1;
        if (si > 0) {
            int c0 = tg[b * SS + si];
            int c1 = tg[b * SS + si - 1];
            return (c0 != 0 && c0 != c1) ? 1.0f : 0.0f;
        }
    }
    return 0.0f;
}

// ---- forward pair body (2 time steps); RN: renormalize mantissas ----
template <bool RN>
__device__ __forceinline__ void fpair(float a[7], int& E,
                                      const float* rowA, const float* rowB,
                                      const float skA[9], int lane) {
    const float4* pA = (const float4*)rowA;
    const float4* pB = (const float4*)rowB;
    float4 A0 = pA[0], A1 = pA[1], A2 = pA[2];
    float4 B0 = pB[0], B1 = pB[1], B2 = pB[2];
    float eA[9] = {A0.y, A0.z, A0.w, A1.x, A1.y, A1.z, A1.w, A2.x, A2.y};
    float eB[7] = {B0.w, B1.x, B1.y, B1.z, B1.w, B2.x, B2.y};

    float h3 = __shfl_up_sync(~0u, a[3], 1);
    float h4 = __shfl_up_sync(~0u, a[4], 1);
    float h5 = __shfl_up_sync(~0u, a[5], 1);
    float h6 = __shfl_up_sync(~0u, a[6], 1);
    int   Ep = __shfl_up_sync(~0u, E, 1);
    if (lane == 0) { h3 = 0.0f; h4 = 0.0f; h5 = 0.0f; h6 = 0.0f; }

    int Em = (E > Ep) ? E : Ep;
    float sa = pow2_clamped(E - Em);
    float sp = pow2_clamped(Ep - Em);
    float X[11];
    X[0] = h3 * sp; X[1] = h4 * sp; X[2] = h5 * sp; X[3] = h6 * sp;
#pragma unroll
    for (int j = 0; j < 7; j++) X[4 + j] = a[j] * sa;

    float bt[9];
#pragma unroll
    for (int i = 0; i < 9; i++)
        bt[i] = fmaf(skA[i], X[i], X[i + 2] + X[i + 1]) * eA[i];
    float n[7];
#pragma unroll
    for (int j = 0; j < 7; j++)
        n[j] = fmaf(skA[j + 2], bt[j], bt[j + 2] + bt[j + 1]) * eB[j];

    if (RN) {
        float mm = fmaxf(fmaxf(fmaxf(n[0], n[1]), fmaxf(n[2], n[3])),
                         fmaxf(fmaxf(n[4], n[5]), n[6]));
        unsigned ub = __float_as_uint(mm) >> 23;
        int shift = 127 - (int)ub;          // ub=0 (dead lane) -> 127, exact
        float f = __uint_as_float((unsigned)(shift + 127) << 23);
        E = Em - shift;
#pragma unroll
        for (int j = 0; j < 7; j++) a[j] = n[j] * f;
    } else {
        E = Em;
#pragma unroll
        for (int j = 0; j < 7; j++) a[j] = n[j];
    }
}

// ---- backward pair body ----
template <bool RN>
__device__ __forceinline__ void bpair(float u[7], int& E,
                                      const float* rowA, const float* rowB,
                                      const float sB9[9], int lane) {
    const float4* pA = (const float4*)rowA;
    const float4* pB = (const float4*)rowB;
    float4 A0 = pA[0], A1 = pA[1], A2 = pA[2];
    float4 B0 = pB[0], B1 = pB[1], B2 = pB[2];
    float eA[9] = {A0.w, A1.x, A1.y, A1.z, A1.w, A2.x, A2.y, A2.z, A2.w};
    float eB[7] = {B0.w, B1.x, B1.y, B1.z, B1.w, B2.x, B2.y};

    float q0 = __shfl_down_sync(~0u, u[0], 1);
    float q1 = __shfl_down_sync(~0u, u[1], 1);
    float q2 = __shfl_down_sync(~0u, u[2], 1);
    float q3 = __shfl_down_sync(~0u, u[3], 1);
    int   Eq = __shfl_down_sync(~0u, E, 1);
    if (lane == 31) { q0 = 0.0f; q1 = 0.0f; q2 = 0.0f; q3 = 0.0f; }

    int Em = (E > Eq) ? E : Eq;
    float sa = pow2_clamped(E - Em);
    float sq = pow2_clamped(Eq - Em);
    float X[11];
#pragma unroll
    for (int j = 0; j < 7; j++) X[j] = u[j] * sa;
    X[7] = q0 * sq; X[8] = q1 * sq; X[9] = q2 * sq; X[10] = q3 * sq;

    float v[9];
#pragma unroll
    for (int i = 0; i < 9; i++)
        v[i] = fmaf(sB9[i], X[i + 2], X[i] + X[i + 1]) * eA[i];
    float n[7];
#pragma unroll
    for (int j = 0; j < 7; j++)
        n[j] = fmaf(sB9[j], v[j + 2], v[j] + v[j + 1]) * eB[j];

    if (RN) {
        float mm = fmaxf(fmaxf(fmaxf(n[0], n[1]), fmaxf(n[2], n[3])),
                         fmaxf(fmaxf(n[4], n[5]), n[6]));
        unsigned ub = __float_as_uint(mm) >> 23;
        int shift = 127 - (int)ub;
        float f = __uint_as_float((unsigned)(shift + 127) << 23);
        E = Em - shift;
#pragma unroll
        for (int j = 0; j < 7; j++) u[j] = n[j] * f;
    } else {
        E = Em;
#pragma unroll
        for (int j = 0; j < 7; j++) u[j] = n[j];
    }
}

__global__ void __launch_bounds__(384, 1)
ctc_all(const float* __restrict__ logp,
        const int* __restrict__ targets,
        const int* __restrict__ input_lens,
        const int* __restrict__ target_lens,
        float* __restrict__ out) {
    extern __shared__ __align__(16) float dsm[];
    const int bid = blockIdx.x;
    const int tid = threadIdx.x;

    if (bid >= BB) {
        // ================= persistent prep CTA =================
        const int k = bid - BB;                 // 0..115
        float* rows = dsm;                      // 8 * CC floats staging
        for (int w = k; w < BB * NTG; w += NPREP) {
            int b = w & 31;
            int pr = w >> 5;
            int tg = (pr & 1) ? (NTG - 1 - (pr >> 1)) : (pr >> 1);
            int t0 = tg * 8;
            // stage 8 logp rows (32KB) into SMEM
            for (int idx = tid; idx < 8 * (CC / 4); idx += 384) {
                int r = idx / (CC / 4), c4 = idx - r * (CC / 4);
                ((float4*)rows)[r * (CC / 4) + c4] =
                    ((const float4*)(logp + ((long)(t0 + r) * BB + b) * CC))[c4];
            }
            __syncthreads();
            // one thread per table column q
            int q = tid;                        // 0..383
            int lane = q / 12, j = q - lane * 12;
            int l = 7 * lane - 3 + j;
            int Lv = 2 * target_lens[b] + 1;
            bool valid = (l >= 0 && l < Lv);
            int lbl = (valid && (l & 1)) ? targets[b * SS + (l >> 1)] : 0;
#pragma unroll
            for (int r = 0; r < 8; r++) {
                float v = valid ? fast_ex2(rows[r * CC + lbl] * LOG2E_F) : 0.0f;
                g_E[b][t0 + r][q] = v;
            }
            __threadfence();
            __syncthreads();
            if (tid == 0)
                asm volatile("st.release.gpu.global.u32 [%0], %1;"
                             :: "l"(&g_ready[b][tg]), "r"(1) : "memory");
        }
        return;
    }

    // ===================== scan CTA (4 warps) ==============================
    if (tid >= 128) return;
    float* ringF = dsm;
    float* ringB = dsm + NSLOT * CHUNK_F;
    float* xu = ringB + NSLOT * CHUNK_F;        // 256
    int* xE = (int*)(xu + 256);                 // 32
    uint64_t* mbFf = (uint64_t*)(xE + 32);      // full F [3]
    uint64_t* mbFe = mbFf + NSLOT;              // empty F [3]
    uint64_t* mbBf = mbFe + NSLOT;              // full B [3]
    uint64_t* mbBe = mbBf + NSLOT;              // empty B [3]

    const int b = bid;
    const int wid = tid >> 5;
    const int lane = tid & 31;
    const int p = 7 * lane;

    const int il = input_lens[b];
    const int tl = target_lens[b];
    const int Lv = 2 * tl + 1;
    const int end1 = 2 * tl, end2 = 2 * tl - 1;
    const int m = ((il - 1) >> 1) & ~1;         // even forward step count
    int remB = il - 2 - m; if (remB < 0) remB = 0;
    const int tailB = remB & 1;
    const int bLo = m + 1 + tailB;
    int cntB = il - 1 - bLo; if (cntB < 0) cntB = 0;
    const bool combine = (il > 1);
    const int nChF = (m + CHR - 1) / CHR;
    const int nChB = (cntB + CHR - 1) / CHR;

    if (tid == 0) {
        for (int q = 0; q < NSLOT; q++) {
            mbar_init(&mbFf[q], 1); mbar_init(&mbFe[q], 1);
            mbar_init(&mbBf[q], 1); mbar_init(&mbBe[q], 1);
        }
        asm volatile("fence.proxy.async.shared::cta;" ::: "memory");
    }
    __syncthreads();

    if (wid == 2) {
        // ---------- forward prefetcher ----------
        if (lane == 0) {
            for (int c = 0; c < nChF; c++) {
                int slot = c % NSLOT;
                mbar_wait(&mbFe[slot], (uint32_t)(((c / NSLOT) & 1) ^ 1));
                int t0r = 1 + CHR * c;
                int rows_c = m - CHR * c; if (rows_c > CHR) rows_c = CHR;
                wait_groups(b, t0r >> 3, (t0r + rows_c - 1) >> 3);
                bulk_in(s2u(ringF) + slot * (CHUNK_F * 4), &g_E[b][t0r][0],
                        rows_c * RB, &mbFf[slot]);
            }
        }
        return;
    }
    if (wid == 3) {
        // ---------- backward prefetcher ----------
        if (lane == 0) {
            for (int c = 0; c < nChB; c++) {
                int slot = c % NSLOT;
                mbar_wait(&mbBe[slot], (uint32_t)(((c / NSLOT) & 1) ^ 1));
                int hi = il - 2 - CHR * c;
                int lo = hi - CHR + 1; if (lo < bLo) lo = bLo;
                wait_groups(b, lo >> 3, hi >> 3);
                bulk_in(s2u(ringB) + slot * (CHUNK_F * 4), &g_E[b][lo][0],
                        (hi - lo + 1) * RB, &mbBf[slot]);
            }
            // ensure every group was produced this run, then reset flags
            wait_groups(b, 0, NTG - 1);
        }
        __syncwarp();
        for (int i = lane; i < NTG; i += 32) g_ready[b][i] = 0;
        return;
    }

    if (wid == 0) {
        // ================= forward consumer =================
        float skA[9];
#pragma unroll
        for (int i = 0; i < 9; i++) skA[i] = skip_into(targets, b, Lv, p - 2 + i);

        float a[7];
#pragma unroll
        for (int j = 0; j < 7; j++) a[j] = 0.0f;
        int E = 0;
        if (lane == 0) {
            const float* row0 = logp + (long)b * CC;
            a[0] = fast_ex2(row0[0] * LOG2E_F);
            if (Lv > 1) a[1] = fast_ex2(row0[targets[b * SS]] * LOG2E_F);
        }

        for (int c = 0; c < nChF; c++) {
            int slot = c % NSLOT;
            mbar_wait(&mbFf[slot], (uint32_t)((c / NSLOT) & 1));
            int rows_c = m - CHR * c; if (rows_c > CHR) rows_c = CHR;
            int pairs = rows_c >> 1;
            const float* base = ringF + slot * CHUNK_F + lane * 12;
            int q = 0;
            for (; q + 2 <= pairs; q += 2) {
                fpair<false>(a, E, base + (2 * q) * RF, base + (2 * q + 1) * RF, skA, lane);
                fpair<true >(a, E, base + (2 * q + 2) * RF, base + (2 * q + 3) * RF, skA, lane);
            }
            if (q < pairs)
                fpair<true>(a, E, base + (2 * q) * RF, base + (2 * q + 1) * RF, skA, lane);
            if (lane == 0) mbar_arrive(&mbFe[slot]);
        }

        asm volatile("bar.sync 1, 64;" ::: "memory");   // meet

        float g[7];
        int Egam;
        if (combine) {
            float uu[7];
#pragma unroll
            for (int j = 0; j < 7; j++) uu[j] = xu[lane * 8 + j];
            float u7 = (lane < 31) ? xu[(lane + 1) * 8 + 0] : 0.0f;
            float u8 = (lane < 31) ? xu[(lane + 1) * 8 + 1] : 0.0f;
            int Eb = xE[lane];
            int Ebn = (lane < 31) ? xE[lane + 1] : Eb;
            int Em2 = (Eb > Ebn) ? Eb : Ebn;
            float su = pow2_clamped(Eb - Em2);
            float sn = pow2_clamped(Ebn - Em2);
            u7 *= sn; u8 *= sn;
            float sB[7];
#pragma unroll
            for (int j = 0; j < 7; j++) sB[j] = skip_into(targets, b, Lv, p + j + 2);
#pragma unroll
            for (int j = 0; j < 5; j++)
                g[j] = su * fmaf(sB[j], uu[j + 2], uu[j] + uu[j + 1]);
            g[5] = fmaf(sB[5], u7, su * (uu[5] + uu[6]));
            g[6] = su * uu[6] + fmaf(sB[6], u8, u7);
            Egam = Em2;
        } else {
#pragma unroll
            for (int j = 0; j < 7; j++) {
                int l = p + j;
                g[j] = (l == end1 || l == end2) ? 1.0f : 0.0f;
            }
            Egam = 0;
        }

        float cacc = 0.0f;
#pragma unroll
        for (int j = 0; j < 7; j++) cacc = fmaf(a[j], g[j], cacc);
        int Ec = (cacc > 0.0f) ? (E + Egam) : EDEAD;
#pragma unroll
        for (int o = 16; o > 0; o >>= 1) {
            float co2 = __shfl_xor_sync(~0u, cacc, o);
            int   Eo = __shfl_xor_sync(~0u, Ec, o);
            int   Emx = (Ec > Eo) ? Ec : Eo;
            cacc = cacc * pow2_clamped(Ec - Emx) + co2 * pow2_clamped(Eo - Emx);
            Ec = Emx;
        }
        if (lane == 0) {
            float lv = -(fast_lg2(cacc) + (float)Ec) * LN2_F;
            if (!(lv <= 0.5e30f)) lv = 0.0f;     // zero_infinity (inf/nan)
            g_loss[b] = lv;
            __threadfence();
            int old = atomicAdd(&g_done, 1);
            if (old == BB - 1) {
                float sum = 0.0f;
                for (int i = 0; i < BB; i++) sum += g_loss[i];
                out[0] = sum;
                g_done = 0;                       // reset for next replay
            }
        }
    } else {
        // ================= backward consumer =================
        float sB9[9];
#pragma unroll
        for (int i = 0; i < 9; i++) sB9[i] = skip_into(targets, b, Lv, p + i + 2);

        float u[7];
        int E = 0;
#pragma unroll
        for (int j = 0; j < 7; j++) {
            int l = p + j;
            float v = 0.0f;
            if (il >= 2 && (l == end1 || l == end2)) {
                int lbl = (l & 1) ? targets[b * SS + ((l - 1) >> 1)] : 0;
                v = fast_ex2(logp[((long)(il - 1) * BB + b) * CC + lbl] * LOG2E_F);
            }
            u[j] = v;
        }

        for (int c = 0; c < nChB; c++) {
            int slot = c % NSLOT;
            mbar_wait(&mbBf[slot], (uint32_t)((c / NSLOT) & 1));
            int hi = il - 2 - CHR * c;
            int lo = hi - CHR + 1; if (lo < bLo) lo = bLo;
            int rows_c = hi - lo + 1;
            int pairs = rows_c >> 1;
            const float* base = ringB + slot * CHUNK_F + lane * 12;
            int q = 0;
            for (; q + 2 <= pairs; q += 2) {
                bpair<false>(u, E, base + (rows_c - 1 - 2 * q) * RF,
                             base + (rows_c - 2 - 2 * q) * RF, sB9, lane);
                bpair<true >(u, E, base + (rows_c - 3 - 2 * q) * RF,
                             base + (rows_c - 4 - 2 * q) * RF, sB9, lane);
            }
            if (q < pairs)
                bpair<true>(u, E, base + (rows_c - 1 - 2 * q) * RF,
                            base + (rows_c - 2 - 2 * q) * RF, sB9, lane);
            if (lane == 0) mbar_arrive(&mbBe[slot]);
        }

        if (tailB) {
            // one leftover backward step at t = m+1
            const float* rowT = logp + ((long)(m + 1) * BB + b) * CC;
            float e7[7];
            float lpb = __ldg(rowT);
#pragma unroll
            for (int j = 0; j < 7; j++) {
                int l = p + j;
                float lp = -1e30f;
                if (l < Lv) lp = (l & 1) ? __ldg(rowT + targets[b * SS + ((l - 1) >> 1)]) : lpb;
                e7[j] = fast_ex2(lp * LOG2E_F);
            }
            float q0 = __shfl_down_sync(~0u, u[0], 1);
            float q1 = __shfl_down_sync(~0u, u[1], 1);
            int   Eq = __shfl_down_sync(~0u, E, 1);
            if (lane == 31) { q0 = 0.0f; q1 = 0.0f; }
            int Em = (E > Eq) ? E : Eq;
            float sa = pow2_clamped(E - Em);
            float sq = pow2_clamped(Eq - Em);
            float X[9];
#pragma unroll
            for (int j = 0; j < 7; j++) X[j] = u[j] * sa;
            X[7] = q0 * sq; X[8] = q1 * sq;
            float n[7];
#pragma unroll
            for (int j = 0; j < 7; j++)
                n[j] = fmaf(sB9[j], X[j + 2], X[j] + X[j + 1]) * e7[j];
            float mm = fmaxf(fmaxf(fmaxf(n[0], n[1]), fmaxf(n[2], n[3])),
                             fmaxf(fmaxf(n[4], n[5]), n[6]));
            unsigned ub = __float_as_uint(mm) >> 23;
            int shift = 127 - (int)ub;
            float f = __uint_as_float((unsigned)(shift + 127) << 23);
            E = Em - shift;
#pragma unroll
            for (int j = 0; j < 7; j++) u[j] = n[j] * f;
        }

        if (!combine) {                          // il == 1
#pragma unroll
            for (int j = 0; j < 7; j++) {
                int l = p + j;
                u[j] = (l == end1 || l == end2) ? 1.0f : 0.0f;
            }
            E = 0;
        }
#pragma unroll
        for (int j = 0; j < 7; j++) xu[lane * 8 + j] = u[j];
        xu[lane * 8 + 7] = 0.0f;
        xE[lane] = E;
        asm volatile("bar.sync 1, 64;" ::: "memory");   // meet
    }
}

extern "C" void kernel_launch(void* const* d_in, const int* in_sizes, int n_in,
                              void* d_out, int out_size) {
    const float* logp        = (const float*)d_in[0];
    const int*   targets     = (const int*)d_in[1];
    const int*   input_lens  = (const int*)d_in[2];
    const int*   target_lens = (const int*)d_in[3];
    float* out = (float*)d_out;

    cudaFuncSetAttribute(ctc_all, cudaFuncAttributeMaxDynamicSharedMemorySize, SMEM_BYTES);
    ctc_all<<<BB + NPREP, 384, SMEM_BYTES>>>(logp, targets, input_lens, target_lens, out);
}

// round 14
// speedup vs baseline: 2.2176x; 1.6979x over previous
#include <cuda_runtime.h>
#include <cuda_bf16.h>
#include <cstdint>

// CTC loss forward — single kernel, 32 CTAs, no e-table, no prep pass.
// Per CTA (batch b), 320 threads with explicit SMSP placement:
//   wid 2 (SMSP2): forward alpha consumer (t=1..m)
//   wid 3 (SMSP3): backward gamma consumer (t=il-1..m+1), meet in middle
//   wid 0,4,8 (SMSP0): forward producers k=0..2 (static ring slot = k)
//   wid 1,5,9 (SMSP1): backward producers
// Producer: cp.async.bulk logp row (4KB) into 4-deep private staging, gather
// 7 labels + blank via LDS, ex2.approx, write compact 8-float/lane ring row
// (12-float stride -> LDS/STS.128 conflict-free). Consumers: 2 steps/iter
// (redundant halo, halo e via 2 shfls), per-lane block floating point,
// renorm every 2 iters. Last CTA reduces g_loss -> out.

#define TT 1000
#define BB 32
#define CC 1000
#define SS 100
#define CH 8                    // rows per ring chunk
#define ROWF 384                // ring row stride in floats (12/lane)
#define RING_F (3 * CH * ROWF)  // 9216 floats per direction
#define STG_F 1024              // floats per staging buffer (4KB)
#define SMEM_BYTES ((2 * RING_F + 6 * 4 * STG_F + 256) * 4 + 32 * 4 + 36 * 8 + 64)

#define LOG2E_F 1.4426950408889634f
#define LN2_F 0.6931471805599453f
#define NEGF (-1e30f)
#define EDEAD (-(1 << 28))

__device__ float g_loss[BB];
__device__ int g_done;                 // reset each run by last CTA

__device__ __forceinline__ float fast_ex2(float x) {
    float y; asm("ex2.approx.ftz.f32 %0, %1;" : "=f"(y) : "f"(x)); return y;
}
__device__ __forceinline__ float fast_lg2(float x) {
    float y; asm("lg2.approx.f32 %0, %1;" : "=f"(y) : "f"(x)); return y;
}
__device__ __forceinline__ uint32_t s2u(const void* p) {
    return (uint32_t)__cvta_generic_to_shared(p);
}
__device__ __forceinline__ void mbar_init(uint64_t* mb, uint32_t cnt) {
    asm volatile("mbarrier.init.shared.b64 [%0], %1;" :: "r"(s2u(mb)), "r"(cnt) : "memory");
}
__device__ __forceinline__ void mbar_wait(uint64_t* mb, uint32_t parity) {
    asm volatile(
        "{\n\t.reg .pred P;\n\t"
        "WL%=:\n\t"
        "mbarrier.try_wait.parity.acquire.cta.shared::cta.b64 P, [%0], %1, 0x989680;\n\t"
        "@P bra WD%=;\n\t"
        "bra WL%=;\n\t"
        "WD%=:\n\t}"
        :: "r"(s2u(mb)), "r"(parity) : "memory");
}
__device__ __forceinline__ void mbar_arrive(uint64_t* mb) {
    asm volatile("mbarrier.arrive.shared.b64 _, [%0];" :: "r"(s2u(mb)) : "memory");
}
__device__ __forceinline__ void bulk_in(uint32_t dst, const void* src, uint32_t bytes,
                                        uint64_t* mb) {
    asm volatile("mbarrier.arrive.expect_tx.shared.b64 _, [%0], %1;"
                 :: "r"(s2u(mb)), "r"(bytes) : "memory");
    asm volatile("cp.async.bulk.shared::cta.global.mbarrier::complete_tx::bytes "
                 "[%0], [%1], %2, [%3];"
                 :: "r"(dst), "l"(src), "r"(bytes), "r"(s2u(mb)) : "memory");
}
__device__ __forceinline__ float pow2_clamped(int d) {
    int u = 127 + d; if (u < 0) u = 0;
    return __uint_as_float((unsigned)u << 23);
}
__device__ __forceinline__ float skip_into(const int* __restrict__ tg, int b, int Lv, int p) {
    if ((p & 1) && p < Lv) {
        int si = (p - 1) >> 1;
        if (si > 0) {
            int c0 = tg[b * SS + si];
            int c1 = tg[b * SS + si - 1];
            return (c0 != 0 && c0 != c1) ? 1.0f : 0.0f;
        }
    }
    return 0.0f;
}

// ---- forward pair body (2 steps); compact e rows; RN: renormalize ----
template <bool RN>
__device__ __forceinline__ void fpairC(float a[7], int& E,
                                       const float* rowA, const float* rowB,
                                       const float skA[9], int lane) {
    float4 A0 = ((const float4*)rowA)[0], A1 = ((const float4*)rowA)[1];
    float4 B0 = ((const float4*)rowB)[0], B1 = ((const float4*)rowB)[1];
    float ea0 = A0.x, ea1 = A0.y, ea2 = A0.z, ea3 = A0.w;
    float ea4 = A1.x, ea5 = A1.y, ea6 = A1.z;

    float em2 = __shfl_up_sync(~0u, ea5, 1);   // e at p-2
    float em1 = __shfl_up_sync(~0u, ea6, 1);   // e at p-1
    float h3 = __shfl_up_sync(~0u, a[3], 1);
    float h4 = __shfl_up_sync(~0u, a[4], 1);
    float h5 = __shfl_up_sync(~0u, a[5], 1);
    float h6 = __shfl_up_sync(~0u, a[6], 1);
    int   Ep = __shfl_up_sync(~0u, E, 1);
    if (lane == 0) { h3 = 0.0f; h4 = 0.0f; h5 = 0.0f; h6 = 0.0f; em2 = 0.0f; em1 = 0.0f; }

    int Em = (E > Ep) ? E : Ep;
    float sa = pow2_clamped(E - Em);
    float sp = pow2_clamped(Ep - Em);
    float X[11];                     // alpha at p-4 .. p+6
    X[0] = h3 * sp; X[1] = h4 * sp; X[2] = h5 * sp; X[3] = h6 * sp;
#pragma unroll
    for (int j = 0; j < 7; j++) X[4 + j] = a[j] * sa;

    float eA[9] = {em2, em1, ea0, ea1, ea2, ea3, ea4, ea5, ea6};
    float eB[7] = {B0.x, B0.y, B0.z, B0.w, B1.x, B1.y, B1.z};

    float bt[9];
#pragma unroll
    for (int i = 0; i < 9; i++)
        bt[i] = fmaf(skA[i], X[i], X[i + 2] + X[i + 1]) * eA[i];
    float n[7];
#pragma unroll
    for (int j = 0; j < 7; j++)
        n[j] = fmaf(skA[j + 2], bt[j], bt[j + 2] + bt[j + 1]) * eB[j];

    if (RN) {
        float mm = fmaxf(fmaxf(fmaxf(n[0], n[1]), fmaxf(n[2], n[3])),
                         fmaxf(fmaxf(n[4], n[5]), n[6]));
        unsigned ub = __float_as_uint(mm) >> 23;
        int shift = 127 - (int)ub;
        float f = __uint_as_float((unsigned)(shift + 127) << 23);
        E = Em - shift;
#pragma unroll
        for (int j = 0; j < 7; j++) a[j] = n[j] * f;
    } else {
        E = Em;
#pragma unroll
        for (int j = 0; j < 7; j++) a[j] = n[j];
    }
}

// ---- backward pair body ----
template <bool RN>
__device__ __forceinline__ void bpairC(float u[7], int& E,
                                       const float* rowA, const float* rowB,
                                       const float sB9[9], int lane) {
    float4 A0 = ((const float4*)rowA)[0], A1 = ((const float4*)rowA)[1];
    float4 B0 = ((const float4*)rowB)[0], B1 = ((const float4*)rowB)[1];
    float ea0 = A0.x, ea1 = A0.y, ea2 = A0.z, ea3 = A0.w;
    float ea4 = A1.x, ea5 = A1.y, ea6 = A1.z;

    float e7 = __shfl_down_sync(~0u, ea0, 1);  // e at p+7
    float e8 = __shfl_down_sync(~0u, ea1, 1);  // e at p+8
    float q0 = __shfl_down_sync(~0u, u[0], 1);
    float q1 = __shfl_down_sync(~0u, u[1], 1);
    float q2 = __shfl_down_sync(~0u, u[2], 1);
    float q3 = __shfl_down_sync(~0u, u[3], 1);
    int   Eq = __shfl_down_sync(~0u, E, 1);
    if (lane == 31) { q0 = 0.0f; q1 = 0.0f; q2 = 0.0f; q3 = 0.0f; e7 = 0.0f; e8 = 0.0f; }

    int Em = (E > Eq) ? E : Eq;
    float sa = pow2_clamped(E - Em);
    float sq = pow2_clamped(Eq - Em);
    float X[11];                     // u at p .. p+10
#pragma unroll
    for (int j = 0; j < 7; j++) X[j] = u[j] * sa;
    X[7] = q0 * sq; X[8] = q1 * sq; X[9] = q2 * sq; X[10] = q3 * sq;

    float eA[9] = {ea0, ea1, ea2, ea3, ea4, ea5, ea6, e7, e8};
    float eB[7] = {B0.x, B0.y, B0.z, B0.w, B1.x, B1.y, B1.z};

    float v[9];
#pragma unroll
    for (int i = 0; i < 9; i++)
        v[i] = fmaf(sB9[i], X[i + 2], X[i] + X[i + 1]) * eA[i];
    float n[7];
#pragma unroll
    for (int j = 0; j < 7; j++)
        n[j] = fmaf(sB9[j], v[j + 2], v[j] + v[j + 1]) * eB[j];

    if (RN) {
        float mm = fmaxf(fmaxf(fmaxf(n[0], n[1]), fmaxf(n[2], n[3])),
                         fmaxf(fmaxf(n[4], n[5]), n[6]));
        unsigned ub = __float_as_uint(mm) >> 23;
        int shift = 127 - (int)ub;
        float f = __uint_as_float((unsigned)(shift + 127) << 23);
        E = Em - shift;
#pragma unroll
        for (int j = 0; j < 7; j++) u[j] = n[j] * f;
    } else {
        E = Em;
#pragma unroll
        for (int j = 0; j < 7; j++) u[j] = n[j];
    }
}

// ---- producer warp: stream rows via cp.async.bulk, gather+exp into ring ----
__device__ void producer(const float* __restrict__ logp, int b, int il, int Lv,
                         const int* __restrict__ targets,
                         float* ring, uint64_t* mbf, uint64_t* mbe,
                         float* stg, uint64_t* mbs,
                         int N, int k, int lane, bool fwd) {
    int off[7], msk[7], isl[7];
#pragma unroll
    for (int j = 0; j < 7; j++) {
        int l = 7 * lane + j;
        off[j] = 0; msk[j] = 0; isl[j] = 0;
        if (l < Lv) {
            msk[j] = 1;
            if (l & 1) { isl[j] = 1; off[j] = targets[b * SS + (l >> 1)]; }
        }
    }
    const int nch = (N + CH - 1) / CH;
    const uint32_t stg_u = s2u(stg);

    // issue cursor over this warp's rows (chunks k, k+3, ...)
    int ci = k, ri = 0, nissued = 0;
    while (nissued < 4 && ci < nch) {
        int i = ci * CH + ri;
        int t = fwd ? (1 + i) : (il - 2 - i);
        if (lane == 0)
            bulk_in(stg_u + (nissued & 3) * (STG_F * 4),
                    logp + ((long)t * BB + b) * CC, CC * 4, &mbs[nissued & 3]);
        nissued++;
        ri++;
        int rc = N - ci * CH; if (rc > CH) rc = CH;
        if (ri >= rc) { ci += 3; ri = 0; }
    }

    int pi = 0;
    for (int c = k; c < nch; c += 3) {
        int rows_c = N - c * CH; if (rows_c > CH) rows_c = CH;
        mbar_wait(&mbe[k], (uint32_t)(((c / 3) & 1) ^ 1));
        for (int r = 0; r < rows_c; r++) {
            mbar_wait(&mbs[pi & 3], (uint32_t)((pi >> 2) & 1));
            const float* buf = stg + (pi & 3) * STG_F;
            float blk = buf[0];
            float o[8];
#pragma unroll
            for (int j = 0; j < 7; j++) {
                float v = 0.0f;
                if (msk[j]) {
                    float lp = isl[j] ? buf[off[j]] : blk;
                    v = fast_ex2(lp * LOG2E_F);
                }
                o[j] = v;
            }
            o[7] = 0.0f;
            float* dst = ring + (k * CH + r) * ROWF + lane * 12;
            ((float4*)dst)[0] = make_float4(o[0], o[1], o[2], o[3]);
            ((float4*)dst)[1] = make_float4(o[4], o[5], o[6], o[7]);
            __syncwarp();
            if (ci < nch) {
                int i = ci * CH + ri;
                int t = fwd ? (1 + i) : (il - 2 - i);
                if (lane == 0) {
                    asm volatile("fence.proxy.async.shared::cta;" ::: "memory");
                    bulk_in(stg_u + (nissued & 3) * (STG_F * 4),
                            logp + ((long)t * BB + b) * CC, CC * 4, &mbs[nissued & 3]);
                }
                nissued++;
                ri++;
                int rc = N - ci * CH; if (rc > CH) rc = CH;
                if (ri >= rc) { ci += 3; ri = 0; }
            }
            pi++;
        }
        __syncwarp();
        if (lane == 0) mbar_arrive(&mbf[k]);
    }
}

__global__ void __launch_bounds__(320, 1)
ctc_all(const float* __restrict__ logp,
        const int* __restrict__ targets,
        const int* __restrict__ input_lens,
        const int* __restrict__ target_lens,
        float* __restrict__ out) {
    extern __shared__ __align__(16) float dsm[];
    float* ringF = dsm;                               // 9216
    float* ringB = dsm + RING_F;                      // 9216
    float* stage = dsm + 2 * RING_F;                  // 6*4*1024
    float* xu = stage + 6 * 4 * STG_F;                // 256
    int* xE = (int*)(xu + 256);                       // 32
    uint64_t* mbFf = (uint64_t*)(xE + 32);
    uint64_t* mbFe = mbFf + 3;
    uint64_t* mbBf = mbFe + 3;
    uint64_t* mbBe = mbBf + 3;
    uint64_t* mbS  = mbBe + 3;                        // 6 warps x 4

    const int b = blockIdx.x;
    const int tid = threadIdx.x;
    const int wid = tid >> 5;
    const int lane = tid & 31;
    const int p = 7 * lane;

    const int il = input_lens[b];
    const int tl = target_lens[b];
    const int Lv = 2 * tl + 1;
    const int end1 = 2 * tl, end2 = 2 * tl - 1;
    const int m = ((il - 1) >> 1) & ~1;               // even forward step count
    int remB = il - 2 - m; if (remB < 0) remB = 0;
    const int tailB = remB & 1;
    int nB = remB - tailB;                            // even backward ring rows
    const bool combine = (il > 1);

    if (tid == 0) {
        for (int q = 0; q < 3; q++) {
            mbar_init(&mbFf[q], 1); mbar_init(&mbFe[q], 1);
            mbar_init(&mbBf[q], 1); mbar_init(&mbBe[q], 1);
        }
        for (int q = 0; q < 24; q++) mbar_init(&mbS[q], 1);
        asm volatile("fence.proxy.async.shared::cta;" ::: "memory");
    }
    __syncthreads();

    if (wid == 0 || wid == 4 || wid == 8) {
        int k = wid >> 2;
        producer(logp, b, il, Lv, targets, ringF, mbFf, mbFe,
                 stage + k * 4 * STG_F, mbS + k * 4, m, k, lane, true);
        return;
    }
    if (wid == 1 || wid == 5 || wid == 9) {
        int k = wid >> 2;
        producer(logp, b, il, Lv, targets, ringB, mbBf, mbBe,
                 stage + (3 + k) * 4 * STG_F, mbS + (3 + k) * 4, nB, k, lane, false);
        return;
    }
    if (wid >= 4) return;   // wids 6,7 idle

    if (wid == 2) {
        // ================= forward consumer (SMSP2, alone) =================
        float skA[9];
#pragma unroll
        for (int i = 0; i < 9; i++) skA[i] = skip_into(targets, b, Lv, p - 2 + i);

        float a[7];
#pragma unroll
        for (int j = 0; j < 7; j++) a[j] = 0.0f;
        int E = 0;
        if (lane == 0) {
            const float* row0 = logp + (long)b * CC;
            a[0] = fast_ex2(row0[0] * LOG2E_F);
            if (Lv > 1) a[1] = fast_ex2(row0[targets[b * SS]] * LOG2E_F);
        }

        const int nch = (m + CH - 1) / CH;
        for (int c = 0; c < nch; c++) {
            int slot = c % 3;
            mbar_wait(&mbFf[slot], (uint32_t)((c / 3) & 1));
            int rows_c = m - c * CH; if (rows_c > CH) rows_c = CH;
            int pairs = rows_c >> 1;
            const float* base = ringF + slot * CH * ROWF + lane * 12;
            int q = 0;
            for (; q + 2 <= pairs; q += 2) {
                fpairC<false>(a, E, base + (2 * q) * ROWF, base + (2 * q + 1) * ROWF, skA, lane);
                fpairC<true >(a, E, base + (2 * q + 2) * ROWF, base + (2 * q + 3) * ROWF, skA, lane);
            }
            if (q < pairs)
                fpairC<true>(a, E, base + (2 * q) * ROWF, base + (2 * q + 1) * ROWF, skA, lane);
            __syncwarp();
            if (lane == 0) mbar_arrive(&mbFe[slot]);
        }

        asm volatile("bar.sync 1, 64;" ::: "memory");   // meet

        float g[7];
        int Egam;
        if (combine) {
            float uu[7];
#pragma unroll
            for (int j = 0; j < 7; j++) uu[j] = xu[lane * 8 + j];
            float u7 = (lane < 31) ? xu[(lane + 1) * 8 + 0] : 0.0f;
            float u8 = (lane < 31) ? xu[(lane + 1) * 8 + 1] : 0.0f;
            int Eb = xE[lane];
            int Ebn = (lane < 31) ? xE[lane + 1] : Eb;
            int Em2 = (Eb > Ebn) ? Eb : Ebn;
            float su = pow2_clamped(Eb - Em2);
            float sn = pow2_clamped(Ebn - Em2);
            u7 *= sn; u8 *= sn;
            float sB[7];
#pragma unroll
            for (int j = 0; j < 7; j++) sB[j] = skip_into(targets, b, Lv, p + j + 2);
#pragma unroll
            for (int j = 0; j < 5; j++)
                g[j] = su * fmaf(sB[j], uu[j + 2], uu[j] + uu[j + 1]);
            g[5] = fmaf(sB[5], u7, su * (uu[5] + uu[6]));
            g[6] = su * uu[6] + fmaf(sB[6], u8, u7);
            Egam = Em2;
        } else {
#pragma unroll
            for (int j = 0; j < 7; j++) {
                int l = p + j;
                g[j] = (l == end1 || l == end2) ? 1.0f : 0.0f;
            }
            Egam = 0;
        }

        float cacc = 0.0f;
#pragma unroll
        for (int j = 0; j < 7; j++) cacc = fmaf(a[j], g[j], cacc);
        int Ec = (cacc > 0.0f) ? (E + Egam) : EDEAD;
#pragma unroll
        for (int o = 16; o > 0; o >>= 1) {
            float co2 = __shfl_xor_sync(~0u, cacc, o);
            int   Eo = __shfl_xor_sync(~0u, Ec, o);
            int   Emx = (Ec > Eo) ? Ec : Eo;
            cacc = cacc * pow2_clamped(Ec - Emx) + co2 * pow2_clamped(Eo - Emx);
            Ec = Emx;
        }
        if (lane == 0) {
            float lv = -(fast_lg2(cacc) + (float)Ec) * LN2_F;
            if (!(lv <= 0.5e30f)) lv = 0.0f;     // zero_infinity (inf/nan)
            g_loss[b] = lv;
            __threadfence();
            int old = atomicAdd(&g_done, 1);
            if (old == BB - 1) {
                float sum = 0.0f;
                for (int i = 0; i < BB; i++) sum += g_loss[i];
                out[0] = sum;
                g_done = 0;                       // reset for next replay
            }
        }
    } else {
        // ================= backward consumer (SMSP3, alone) ================
        float sB9[9];
#pragma unroll
        for (int i = 0; i < 9; i++) sB9[i] = skip_into(targets, b, Lv, p + i + 2);

        float u[7];
        int E = 0;
#pragma unroll
        for (int j = 0; j < 7; j++) {
            int l = p + j;
            float v = 0.0f;
            if (il >= 2 && (l == end1 || l == end2)) {
                int lbl = (l & 1) ? targets[b * SS + ((l - 1) >> 1)] : 0;
                v = fast_ex2(logp[((long)(il - 1) * BB + b) * CC + lbl] * LOG2E_F);
            }
            u[j] = v;
        }

        const int nch = (nB + CH - 1) / CH;
        for (int c = 0; c < nch; c++) {
            int slot = c % 3;
            mbar_wait(&mbBf[slot], (uint32_t)((c / 3) & 1));
            int rows_c = nB - c * CH; if (rows_c > CH) rows_c = CH;
            int pairs = rows_c >> 1;
            const float* base = ringB + slot * CH * ROWF + lane * 12;
            int q = 0;
            for (; q + 2 <= pairs; q += 2) {
                bpairC<false>(u, E, base + (2 * q) * ROWF, base + (2 * q + 1) * ROWF, sB9, lane);
                bpairC<true >(u, E, base + (2 * q + 2) * ROWF, base + (2 * q + 3) * ROWF, sB9, lane);
            }
            if (q < pairs)
                bpairC<true>(u, E, base + (2 * q) * ROWF, base + (2 * q + 1) * ROWF, sB9, lane);
            __syncwarp();
            if (lane == 0) mbar_arrive(&mbBe[slot]);
        }

        if (tailB) {
            // one leftover backward step at t = m+1
            const float* rowT = logp + ((long)(m + 1) * BB + b) * CC;
            float e7[7];
            float lpb = __ldg(rowT);
#pragma unroll
            for (int j = 0; j < 7; j++) {
                int l = p + j;
                float lp = NEGF;
                if (l < Lv) lp = (l & 1) ? __ldg(rowT + targets[b * SS + ((l - 1) >> 1)]) : lpb;
                e7[j] = fast_ex2(lp * LOG2E_F);
            }
            float q0 = __shfl_down_sync(~0u, u[0], 1);
            float q1 = __shfl_down_sync(~0u, u[1], 1);
            int   Eq = __shfl_down_sync(~0u, E, 1);
            if (lane == 31) { q0 = 0.0f; q1 = 0.0f; }
            int Em = (E > Eq) ? E : Eq;
            float sa = pow2_clamped(E - Em);
            float sq = pow2_clamped(Eq - Em);
            float X[9];
#pragma unroll
            for (int j = 0; j < 7; j++) X[j] = u[j] * sa;
            X[7] = q0 * sq; X[8] = q1 * sq;
            float n[7];
#pragma unroll
            for (int j = 0; j < 7; j++)
                n[j] = fmaf(sB9[j], X[j + 2], X[j] + X[j + 1]) * e7[j];
            float mm = fmaxf(fmaxf(fmaxf(n[0], n[1]), fmaxf(n[2], n[3])),
                             fmaxf(fmaxf(n[4], n[5]), n[6]));
            unsigned ub = __float_as_uint(mm) >> 23;
            int shift = 127 - (int)ub;
            float f = __uint_as_float((unsigned)(shift + 127) << 23);
            E = Em - shift;
#pragma unroll
            for (int j = 0; j < 7; j++) u[j] = n[j] * f;
        }

        if (!combine) {                          // il == 1
#pragma unroll
            for (int j = 0; j < 7; j++) {
                int l = p + j;
                u[j] = (l == end1 || l == end2) ? 1.0f : 0.0f;
            }
            E = 0;
        }
#pragma unroll
        for (int j = 0; j < 7; j++) xu[lane * 8 + j] = u[j];
        xu[lane * 8 + 7] = 0.0f;
        xE[lane] = E;
        asm volatile("bar.sync 1, 64;" ::: "memory");   // meet
    }
}

extern "C" void kernel_launch(void* const* d_in, const int* in_sizes, int n_in,
                              void* d_out, int out_size) {
    const float* logp        = (const float*)d_in[0];
    const int*   targets     = (const int*)d_in[1];
    const int*   input_lens  = (const int*)d_in[2];
    const int*   target_lens = (const int*)d_in[3];
    float* out = (float*)d_out;

    cudaFuncSetAttribute(ctc_all, cudaFuncAttributeMaxDynamicSharedMemorySize, SMEM_BYTES);
    ctc_all<<<BB, 320, SMEM_BYTES>>>(logp, targets, input_lens, target_lens, out);
}

// round 15
// speedup vs baseline: 3.1370x; 1.4146x over previous
#include <cuda_runtime.h>
#include <cuda_bf16.h>
#include <cstdint>

// CTC loss forward: prep kernel (compact e-table) + pure 2-warp scan kernel.
// prep: per (t,b) row, stage logp row in SMEM, write COMPACT 8-float/lane
//       table g_E[b][t][lane*8+j] = e at trellis position 7*lane+j (j<7,
//       0 if invalid; j=7 pad). 1KB/row (was 1.5KB) — prep is LTS-bound.
// scan: 32 CTAs x 64 threads; wid0 = forward alpha (t=1..m), wid1 = backward
//       gamma (t=il-1..m+1), meet-in-the-middle; cp.async.bulk 3-slot rings
//       (16 rows/chunk); 2 steps per iteration with halo e reconstructed via
//       2 shfls (R14-validated bodies); per-lane block floating point,
//       renorm every 2 iterations. Last scan CTA reduces g_loss -> out.

#define TT 1000
#define BB 32
#define CC 1000
#define SS 100
#define RF 256                 // floats per table row (32 lanes x 8)
#define RB (RF * 4)            // 1024 bytes
#define CHR 16                 // rows per scan chunk (even)
#define NSLOT 3
#define CHUNK_F (CHR * RF)     // 4096 floats
#define SCAN_SMEM ((2 * NSLOT * CHUNK_F + 256) * 4 + 32 * 4 + 2 * NSLOT * 8)
#define PREP_SMEM (8 * CC * 4)

#define LOG2E_F 1.4426950408889634f
#define LN2_F 0.6931471805599453f
#define NEGF (-1e30f)
#define EDEAD (-(1 << 28))

__device__ float g_E[BB][TT][RF];      // 32.8 MB static scratch
__device__ float g_loss[BB];
__device__ int g_done;                 // reset by last scan CTA each run

__device__ __forceinline__ float fast_ex2(float x) {
    float y; asm("ex2.approx.ftz.f32 %0, %1;" : "=f"(y) : "f"(x)); return y;
}
__device__ __forceinline__ float fast_lg2(float x) {
    float y; asm("lg2.approx.f32 %0, %1;" : "=f"(y) : "f"(x)); return y;
}
__device__ __forceinline__ uint32_t s2u(const void* p) {
    return (uint32_t)__cvta_generic_to_shared(p);
}
__device__ __forceinline__ void mbar_init(uint64_t* mb, uint32_t cnt) {
    asm volatile("mbarrier.init.shared.b64 [%0], %1;" :: "r"(s2u(mb)), "r"(cnt) : "memory");
}
__device__ __forceinline__ void mbar_wait(uint64_t* mb, uint32_t parity) {
    asm volatile(
        "{\n\t.reg .pred P;\n\t"
        "WL%=:\n\t"
        "mbarrier.try_wait.parity.acquire.cta.shared::cta.b64 P, [%0], %1, 0x989680;\n\t"
        "@P bra WD%=;\n\t"
        "bra WL%=;\n\t"
        "WD%=:\n\t}"
        :: "r"(s2u(mb)), "r"(parity) : "memory");
}
__device__ __forceinline__ void bulk_in(uint32_t dst, const void* src, uint32_t bytes,
                                        uint64_t* mb) {
    asm volatile("mbarrier.arrive.expect_tx.shared.b64 _, [%0], %1;"
                 :: "r"(s2u(mb)), "r"(bytes) : "memory");
    asm volatile("cp.async.bulk.shared::cta.global.mbarrier::complete_tx::bytes "
                 "[%0], [%1], %2, [%3];"
                 :: "r"(dst), "l"(src), "r"(bytes), "r"(s2u(mb)) : "memory");
}
__device__ __forceinline__ float pow2_clamped(int d) {
    int u = 127 + d; if (u < 0) u = 0;
    return __uint_as_float((unsigned)u << 23);
}
__device__ __forceinline__ float skip_into(const int* __restrict__ tg, int b, int Lv, int p) {
    if ((p & 1) && p < Lv) {
        int si = (p - 1) >> 1;
        if (si > 0) {
            int c0 = tg[b * SS + si];
            int c1 = tg[b * SS + si - 1];
            return (c0 != 0 && c0 != c1) ? 1.0f : 0.0f;
        }
    }
    return 0.0f;
}

// ---------------- prep: compact e-table ----------------
__global__ void ctc_prep(const float* __restrict__ logp,
                         const int* __restrict__ targets,
                         const int* __restrict__ target_lens) {
    extern __shared__ __align__(16) float rows[];       // 8 * CC floats
    const int b = blockIdx.y, t0 = blockIdx.x * 8, tid = threadIdx.x;
    const int Lv = 2 * target_lens[b] + 1;
    for (int idx = tid; idx < 8 * (CC / 4); idx += 256) {
        int r = idx / (CC / 4), c4 = idx - r * (CC / 4);
        ((float4*)rows)[r * (CC / 4) + c4] =
            ((const float4*)(logp + ((long)(t0 + r) * BB + b) * CC))[c4];
    }
    __syncthreads();
    // one thread per table column; loop over the 8 rows
    int q = tid;                        // 0..255
    int lane = q >> 3, j = q & 7;
    int l = 7 * lane + j;
    bool valid = (j < 7) && (l < Lv);
    int lbl = (valid && (l & 1)) ? targets[b * SS + (l >> 1)] : 0;
#pragma unroll
    for (int r = 0; r < 8; r++) {
        float v = valid ? fast_ex2(rows[r * CC + lbl] * LOG2E_F) : 0.0f;
        g_E[b][t0 + r][q] = v;
    }
}

// ---- forward pair body (2 steps), compact rows; RN: renormalize ----
template <bool RN>
__device__ __forceinline__ void fpairC(float a[7], int& E,
                                       const float* rowA, const float* rowB,
                                       const float skA[9], int lane) {
    float4 A0 = ((const float4*)rowA)[0], A1 = ((const float4*)rowA)[1];
    float4 B0 = ((const float4*)rowB)[0], B1 = ((const float4*)rowB)[1];
    float ea0 = A0.x, ea1 = A0.y, ea2 = A0.z, ea3 = A0.w;
    float ea4 = A1.x, ea5 = A1.y, ea6 = A1.z;

    float em2 = __shfl_up_sync(~0u, ea5, 1);   // e at p-2
    float em1 = __shfl_up_sync(~0u, ea6, 1);   // e at p-1
    float h3 = __shfl_up_sync(~0u, a[3], 1);
    float h4 = __shfl_up_sync(~0u, a[4], 1);
    float h5 = __shfl_up_sync(~0u, a[5], 1);
    float h6 = __shfl_up_sync(~0u, a[6], 1);
    int   Ep = __shfl_up_sync(~0u, E, 1);
    if (lane == 0) { h3 = 0.0f; h4 = 0.0f; h5 = 0.0f; h6 = 0.0f; em2 = 0.0f; em1 = 0.0f; }

    int Em = (E > Ep) ? E : Ep;
    float sa = pow2_clamped(E - Em);
    float sp = pow2_clamped(Ep - Em);
    float X[11];                     // alpha at p-4 .. p+6
    X[0] = h3 * sp; X[1] = h4 * sp; X[2] = h5 * sp; X[3] = h6 * sp;
#pragma unroll
    for (int j = 0; j < 7; j++) X[4 + j] = a[j] * sa;

    float eA[9] = {em2, em1, ea0, ea1, ea2, ea3, ea4, ea5, ea6};
    float eB[7] = {B0.x, B0.y, B0.z, B0.w, B1.x, B1.y, B1.z};

    float bt[9];                     // alpha' at p-2 .. p+6
#pragma unroll
    for (int i = 0; i < 9; i++)
        bt[i] = fmaf(skA[i], X[i], X[i + 2] + X[i + 1]) * eA[i];
    float n[7];                      // alpha'' at p .. p+6
#pragma unroll
    for (int j = 0; j < 7; j++)
        n[j] = fmaf(skA[j + 2], bt[j], bt[j + 2] + bt[j + 1]) * eB[j];

    if (RN) {
        float mm = fmaxf(fmaxf(fmaxf(n[0], n[1]), fmaxf(n[2], n[3])),
                         fmaxf(fmaxf(n[4], n[5]), n[6]));
        unsigned ub = __float_as_uint(mm) >> 23;
        int shift = 127 - (int)ub;          // ub=0 (dead lane) -> 127, exact
        float f = __uint_as_float((unsigned)(shift + 127) << 23);
        E = Em - shift;
#pragma unroll
        for (int j = 0; j < 7; j++) a[j] = n[j] * f;
    } else {
        E = Em;
#pragma unroll
        for (int j = 0; j < 7; j++) a[j] = n[j];
    }
}

// ---- backward pair body ----
template <bool RN>
__device__ __forceinline__ void bpairC(float u[7], int& E,
                                       const float* rowA, const float* rowB,
                                       const float sB9[9], int lane) {
    float4 A0 = ((const float4*)rowA)[0], A1 = ((const float4*)rowA)[1];
    float4 B0 = ((const float4*)rowB)[0], B1 = ((const float4*)rowB)[1];
    float ea0 = A0.x, ea1 = A0.y, ea2 = A0.z, ea3 = A0.w;
    float ea4 = A1.x, ea5 = A1.y, ea6 = A1.z;

    float e7 = __shfl_down_sync(~0u, ea0, 1);  // e at p+7
    float e8 = __shfl_down_sync(~0u, ea1, 1);  // e at p+8
    float q0 = __shfl_down_sync(~0u, u[0], 1);
    float q1 = __shfl_down_sync(~0u, u[1], 1);
    float q2 = __shfl_down_sync(~0u, u[2], 1);
    float q3 = __shfl_down_sync(~0u, u[3], 1);
    int   Eq = __shfl_down_sync(~0u, E, 1);
    if (lane == 31) { q0 = 0.0f; q1 = 0.0f; q2 = 0.0f; q3 = 0.0f; e7 = 0.0f; e8 = 0.0f; }

    int Em = (E > Eq) ? E : Eq;
    float sa = pow2_clamped(E - Em);
    float sq = pow2_clamped(Eq - Em);
    float X[11];                     // u at p .. p+10
#pragma unroll
    for (int j = 0; j < 7; j++) X[j] = u[j] * sa;
    X[7] = q0 * sq; X[8] = q1 * sq; X[9] = q2 * sq; X[10] = q3 * sq;

    float eA[9] = {ea0, ea1, ea2, ea3, ea4, ea5, ea6, e7, e8};
    float eB[7] = {B0.x, B0.y, B0.z, B0.w, B1.x, B1.y, B1.z};

    float v[9];                      // gamma_tA at p .. p+8
#pragma unroll
    for (int i = 0; i < 9; i++)
        v[i] = fmaf(sB9[i], X[i + 2], X[i] + X[i + 1]) * eA[i];
    float n[7];
#pragma unroll
    for (int j = 0; j < 7; j++)
        n[j] = fmaf(sB9[j], v[j + 2], v[j] + v[j + 1]) * eB[j];

    if (RN) {
        float mm = fmaxf(fmaxf(fmaxf(n[0], n[1]), fmaxf(n[2], n[3])),
                         fmaxf(fmaxf(n[4], n[5]), n[6]));
        unsigned ub = __float_as_uint(mm) >> 23;
        int shift = 127 - (int)ub;
        float f = __uint_as_float((unsigned)(shift + 127) << 23);
        E = Em - shift;
#pragma unroll
        for (int j = 0; j < 7; j++) u[j] = n[j] * f;
    } else {
        E = Em;
#pragma unroll
        for (int j = 0; j < 7; j++) u[j] = n[j];
    }
}

// ---------------- scan ----------------
__global__ void __launch_bounds__(64, 1)
ctc_scan(const float* __restrict__ logp,
         const int* __restrict__ targets,
         const int* __restrict__ input_lens,
         const int* __restrict__ target_lens,
         float* __restrict__ out) {
    extern __shared__ __align__(16) float dsm[];
    float* ringF = dsm;
    float* ringB = dsm + NSLOT * CHUNK_F;
    float* xu = ringB + NSLOT * CHUNK_F;        // 256
    int* xE = (int*)(xu + 256);                 // 32
    uint64_t* mbF = (uint64_t*)(xE + 32);
    uint64_t* mbB = mbF + NSLOT;

    const int b = blockIdx.x;
    const int tid = threadIdx.x;
    const int wid = tid >> 5;
    const int lane = tid & 31;
    const int p = 7 * lane;

    const int il = input_lens[b];
    const int tl = target_lens[b];
    const int Lv = 2 * tl + 1;
    const int end1 = 2 * tl, end2 = 2 * tl - 1;
    const int m = ((il - 1) >> 1) & ~1;         // even forward step count
    int remB = il - 2 - m; if (remB < 0) remB = 0;
    const int tailB = remB & 1;
    const int bLo = m + 1 + tailB;              // lowest chunked backward row
    int cntB = il - 1 - bLo; if (cntB < 0) cntB = 0;
    const bool combine = (il > 1);

    if (tid == 0) {
        for (int q = 0; q < NSLOT; q++) { mbar_init(&mbF[q], 1); mbar_init(&mbB[q], 1); }
        asm volatile("fence.proxy.async.shared::cta;" ::: "memory");
    }
    __syncthreads();

    if (wid == 0) {
        // ================= forward consumer =================
        float skA[9];
#pragma unroll
        for (int i = 0; i < 9; i++) skA[i] = skip_into(targets, b, Lv, p - 2 + i);

        float a[7];
#pragma unroll
        for (int j = 0; j < 7; j++) a[j] = 0.0f;
        int E = 0;
        if (lane == 0) {
            const float* row0 = logp + (long)b * CC;
            a[0] = fast_ex2(row0[0] * LOG2E_F);
            if (Lv > 1) a[1] = fast_ex2(row0[targets[b * SS]] * LOG2E_F);
        }

        const int nCh = (m + CHR - 1) / CHR;
#pragma unroll
        for (int c = 0; c < NSLOT; c++) {
            if (lane == 0 && c < nCh) {
                int rows_c = m - CHR * c; if (rows_c > CHR) rows_c = CHR;
                bulk_in(s2u(ringF) + c * (CHUNK_F * 4), &g_E[b][1 + CHR * c][0],
                        rows_c * RB, &mbF[c]);
            }
        }

        for (int c = 0; c < nCh; c++) {
            int slot = c % NSLOT;
            mbar_wait(&mbF[slot], (uint32_t)((c / NSLOT) & 1));
            int rows_c = m - CHR * c; if (rows_c > CHR) rows_c = CHR;
            int pairs = rows_c >> 1;
            const float* base = ringF + slot * CHUNK_F + lane * 8;
            int q = 0;
            for (; q + 2 <= pairs; q += 2) {
                fpairC<false>(a, E, base + (2 * q) * RF, base + (2 * q + 1) * RF, skA, lane);
                fpairC<true >(a, E, base + (2 * q + 2) * RF, base + (2 * q + 3) * RF, skA, lane);
            }
            if (q < pairs)
                fpairC<true>(a, E, base + (2 * q) * RF, base + (2 * q + 1) * RF, skA, lane);

            int c2 = c + NSLOT;
            if (lane == 0 && c2 < nCh) {
                int rows_n = m - CHR * c2; if (rows_n > CHR) rows_n = CHR;
                bulk_in(s2u(ringF) + slot * (CHUNK_F * 4), &g_E[b][1 + CHR * c2][0],
                        rows_n * RB, &mbF[slot]);
            }
        }

        __syncthreads();   // meet

        float g[7];
        int Egam;
        if (combine) {
            float uu[7];
#pragma unroll
            for (int j = 0; j < 7; j++) uu[j] = xu[lane * 8 + j];
            float u7 = (lane < 31) ? xu[(lane + 1) * 8 + 0] : 0.0f;
            float u8 = (lane < 31) ? xu[(lane + 1) * 8 + 1] : 0.0f;
            int Eb = xE[lane];
            int Ebn = (lane < 31) ? xE[lane + 1] : Eb;
            int Em2 = (Eb > Ebn) ? Eb : Ebn;
            float su = pow2_clamped(Eb - Em2);
            float sn = pow2_clamped(Ebn - Em2);
            u7 *= sn; u8 *= sn;
            float sB[7];
#pragma unroll
            for (int j = 0; j < 7; j++) sB[j] = skip_into(targets, b, Lv, p + j + 2);
#pragma unroll
            for (int j = 0; j < 5; j++)
                g[j] = su * fmaf(sB[j], uu[j + 2], uu[j] + uu[j + 1]);
            g[5] = fmaf(sB[5], u7, su * (uu[5] + uu[6]));
            g[6] = su * uu[6] + fmaf(sB[6], u8, u7);
            Egam = Em2;
        } else {
#pragma unroll
            for (int j = 0; j < 7; j++) {
                int l = p + j;
                g[j] = (l == end1 || l == end2) ? 1.0f : 0.0f;
            }
            Egam = 0;
        }

        float cacc = 0.0f;
#pragma unroll
        for (int j = 0; j < 7; j++) cacc = fmaf(a[j], g[j], cacc);
        int Ec = (cacc > 0.0f) ? (E + Egam) : EDEAD;
#pragma unroll
        for (int o = 16; o > 0; o >>= 1) {
            float co2 = __shfl_xor_sync(~0u, cacc, o);
            int   Eo = __shfl_xor_sync(~0u, Ec, o);
            int   Emx = (Ec > Eo) ? Ec : Eo;
            cacc = cacc * pow2_clamped(Ec - Emx) + co2 * pow2_clamped(Eo - Emx);
            Ec = Emx;
        }
        if (lane == 0) {
            float lv = -(fast_lg2(cacc) + (float)Ec) * LN2_F;
            if (!(lv <= 0.5e30f)) lv = 0.0f;     // zero_infinity (inf/nan)
            g_loss[b] = lv;
            // last-CTA reduction (deterministic: fixed index-order sum)
            __threadfence();
            int old = atomicAdd(&g_done, 1);
            if (old == BB - 1) {
                float sum = 0.0f;
                for (int i = 0; i < BB; i++) sum += g_loss[i];
                out[0] = sum;
                g_done = 0;                       // reset for next replay
            }
        }
    } else {
        // ================= backward consumer =================
        float sB9[9];
#pragma unroll
        for (int i = 0; i < 9; i++) sB9[i] = skip_into(targets, b, Lv, p + i + 2);

        float u[7];
        int E = 0;
#pragma unroll
        for (int j = 0; j < 7; j++) {
            int l = p + j;
            float v = 0.0f;
            if (il >= 2 && (l == end1 || l == end2)) {
                int lbl = (l & 1) ? targets[b * SS + ((l - 1) >> 1)] : 0;
                v = fast_ex2(logp[((long)(il - 1) * BB + b) * CC + lbl] * LOG2E_F);
            }
            u[j] = v;
        }

        const int nCh = (cntB + CHR - 1) / CHR;
#pragma unroll
        for (int c = 0; c < NSLOT; c++) {
            if (lane == 0 && c < nCh) {
                int hi = il - 2 - CHR * c;
                int lo = hi - CHR + 1; if (lo < bLo) lo = bLo;
                bulk_in(s2u(ringB) + c * (CHUNK_F * 4), &g_E[b][lo][0],
                        (hi - lo + 1) * RB, &mbB[c]);
            }
        }

        for (int c = 0; c < nCh; c++) {
            int slot = c % NSLOT;
            mbar_wait(&mbB[slot], (uint32_t)((c / NSLOT) & 1));
            int hi = il - 2 - CHR * c;
            int lo = hi - CHR + 1; if (lo < bLo) lo = bLo;
            int rows_c = hi - lo + 1;
            int pairs = rows_c >> 1;
            const float* base = ringB + slot * CHUNK_F + lane * 8;
            int q = 0;
            for (; q + 2 <= pairs; q += 2) {
                bpairC<false>(u, E, base + (rows_c - 1 - 2 * q) * RF,
                              base + (rows_c - 2 - 2 * q) * RF, sB9, lane);
                bpairC<true >(u, E, base + (rows_c - 3 - 2 * q) * RF,
                              base + (rows_c - 4 - 2 * q) * RF, sB9, lane);
            }
            if (q < pairs)
                bpairC<true>(u, E, base + (rows_c - 1 - 2 * q) * RF,
                             base + (rows_c - 2 - 2 * q) * RF, sB9, lane);

            int c2 = c + NSLOT;
            if (lane == 0 && c2 < nCh) {
                int hi2 = il - 2 - CHR * c2;
                int lo2 = hi2 - CHR + 1; if (lo2 < bLo) lo2 = bLo;
                bulk_in(s2u(ringB) + slot * (CHUNK_F * 4), &g_E[b][lo2][0],
                        (hi2 - lo2 + 1) * RB, &mbB[slot]);
            }
        }

        if (tailB) {
            // one leftover backward step at t = m+1
            const float* rowT = logp + ((long)(m + 1) * BB + b) * CC;
            float e7[7];
            float lpb = __ldg(rowT);
#pragma unroll
            for (int j = 0; j < 7; j++) {
                int l = p + j;
                float lp = NEGF;
                if (l < Lv) lp = (l & 1) ? __ldg(rowT + targets[b * SS + ((l - 1) >> 1)]) : lpb;
                e7[j] = fast_ex2(lp * LOG2E_F);
            }
            float q0 = __shfl_down_sync(~0u, u[0], 1);
            float q1 = __shfl_down_sync(~0u, u[1], 1);
            int   Eq = __shfl_down_sync(~0u, E, 1);
            if (lane == 31) { q0 = 0.0f; q1 = 0.0f; }
            int Em = (E > Eq) ? E : Eq;
            float sa = pow2_clamped(E - Em);
            float sq = pow2_clamped(Eq - Em);
            float X[9];
#pragma unroll
            for (int j = 0; j < 7; j++) X[j] = u[j] * sa;
            X[7] = q0 * sq; X[8] = q1 * sq;
            float n[7];
#pragma unroll
            for (int j = 0; j < 7; j++)
                n[j] = fmaf(sB9[j], X[j + 2], X[j] + X[j + 1]) * e7[j];
            float mm = fmaxf(fmaxf(fmaxf(n[0], n[1]), fmaxf(n[2], n[3])),
                             fmaxf(fmaxf(n[4], n[5]), n[6]));
            unsigned ub = __float_as_uint(mm) >> 23;
            int shift = 127 - (int)ub;
            float f = __uint_as_float((unsigned)(shift + 127) << 23);
            E = Em - shift;
#pragma unroll
            for (int j = 0; j < 7; j++) u[j] = n[j] * f;
        }

        if (!combine) {                          // il == 1
#pragma unroll
            for (int j = 0; j < 7; j++) {
                int l = p + j;
                u[j] = (l == end1 || l == end2) ? 1.0f : 0.0f;
            }
            E = 0;
        }
#pragma unroll
        for (int j = 0; j < 7; j++) xu[lane * 8 + j] = u[j];
        xu[lane * 8 + 7] = 0.0f;
        xE[lane] = E;
        __syncthreads();   // meet
    }
}

extern "C" void kernel_launch(void* const* d_in, const int* in_sizes, int n_in,
                              void* d_out, int out_size) {
    const float* logp        = (const float*)d_in[0];
    const int*   targets     = (const int*)d_in[1];
    const int*   input_lens  = (const int*)d_in[2];
    const int*   target_lens = (const int*)d_in[3];
    float* out = (float*)d_out;

    cudaFuncSetAttribute(ctc_scan, cudaFuncAttributeMaxDynamicSharedMemorySize, SCAN_SMEM);
    cudaFuncSetAttribute(ctc_prep, cudaFuncAttributeMaxDynamicSharedMemorySize, PREP_SMEM);
    dim3 pg(TT / 8, BB);
    ctc_prep<<<pg, 256, PREP_SMEM>>>(logp, targets, target_lens);
    ctc_scan<<<BB, 64, SCAN_SMEM>>>(logp, targets, input_lens, target_lens, out);
}